// round 8
// baseline (speedup 1.0000x reference)
#include <cuda_runtime.h>
#include <mma.h>
#include <cstdint>

using namespace nvcuda;

namespace {
constexpr int NAGENT = 8;
constexpr int BTOT   = 32768;
constexpr int D      = 128;   // state dim
constexpr int HDIM   = 128;   // hidden
constexpr int ADIM   = 64;    // actions
constexpr int EDIM   = 32;    // constraint hidden

constexpr int TILE_B  = 128;
constexpr int THREADS = 256;  // 8 warps: 4 row-groups (32 rows) x 2 col-groups

constexpr int SW_LD = 132;    // weight buffer pitch (128 cols + 4 skew); 528B rows (16B-aligned)
constexpr int SH_LD = 132;    // activation buffer pitch
constexpr int WC_LD = 36;     // persistent Wc1 pitch (32 cols + 4 skew)
constexpr int BT_LD = 132;    // bias tile pitch

// float offsets into dynamic smem (all *4B are 16B-aligned)
constexpr int OFF_W     = 0;                          // 128*132 floats
constexpr int OFF_HA    = OFF_W   + TILE_B * SW_LD;   // 16896 : H1 / (GEMM3: out cols 0..63, W3 cols 64..127)
constexpr int OFF_HB    = OFF_HA  + TILE_B * SH_LD;   // 33792
constexpr int OFF_WC    = OFF_HB  + TILE_B * SH_LD;   // 50688 : persistent tf32(Wc1) 128x36
constexpr int OFF_BT    = OFF_WC  + D * WC_LD;        // 55296 : 16-row replicated bias tile
constexpr int OFF_B3    = OFF_BT  + 16 * BT_LD;       // 57408
constexpr int OFF_BC1   = OFF_B3  + 64;               // 57472
constexpr int OFF_WS1   = OFF_BC1 + 32;               // 57504
constexpr int OFF_WC2   = OFF_WS1 + 128;              // 57632
constexpr int OFF_SCAL  = OFF_WC2 + 32;               // 57664
constexpr int OFF_CACC  = OFF_SCAL + 128;             // 57792
constexpr int OFF_CONST = OFF_CACC + 128;             // 57920 : [bs1, ws2, bs2, bc2]
constexpr int SMEM_FLOATS = OFF_CONST + 8;            // 57928
constexpr int SMEM_BYTES  = SMEM_FLOATS * 4;          // 231712 B < 232448 B limit
}

__device__ __forceinline__ float to_tf32(float x) {
    // round-to-nearest tf32 (plain truncation would roughly double the error)
    return wmma::__float_to_tf32(x);
}

__device__ __forceinline__ void cp_async16(float* smem_dst, const float4* gmem_src) {
    unsigned saddr = (unsigned)__cvta_generic_to_shared(smem_dst);
    // .cg: bypass L1 (carveout ~0 at 226KB smem anyway), straight to smem via L2
    asm volatile("cp.async.cg.shared.global [%0], [%1], 16;\n" :: "r"(saddr), "l"(gmem_src));
}
__device__ __forceinline__ void cp_async_commit() {
    asm volatile("cp.async.commit_group;\n" ::: "memory");
}
__device__ __forceinline__ void cp_async_wait_all() {
    asm volatile("cp.async.wait_group 0;\n" ::: "memory");
}
__device__ __forceinline__ void cp_async_wait_one_pending() {
    asm volatile("cp.async.wait_group 1;\n" ::: "memory");
}

__global__ __launch_bounds__(THREADS, 1)
void qatten_kernel(const float* __restrict__ states,
                   const float* __restrict__ W1, const float* __restrict__ b1,
                   const float* __restrict__ W2, const float* __restrict__ b2,
                   const float* __restrict__ W3, const float* __restrict__ b3,
                   const float* __restrict__ Ws1, const float* __restrict__ bs1,
                   const float* __restrict__ Ws2, const float* __restrict__ bs2,
                   const float* __restrict__ Wc1, const float* __restrict__ bc1,
                   const float* __restrict__ Wc2, const float* __restrict__ bc2,
                   float* __restrict__ out)
{
    extern __shared__ float4 sm4[];         // float4 => 16B-aligned base guaranteed
    float* sm = (float*)sm4;
    float* sW     = sm + OFF_W;
    float* sHa    = sm + OFF_HA;
    float* sHb    = sm + OFF_HB;
    float* sWc    = sm + OFF_WC;
    float* sBT    = sm + OFF_BT;
    float* sB3    = sm + OFF_B3;
    float* sBc1   = sm + OFF_BC1;
    float* sWs1   = sm + OFF_WS1;
    float* sWc2   = sm + OFF_WC2;
    float* sScal  = sm + OFF_SCAL;
    float* sCacc  = sm + OFF_CACC;
    float* sConst = sm + OFF_CONST;

    const int tid  = threadIdx.x;
    const int warp = tid >> 5;
    const int lane = tid & 31;
    const int b0   = blockIdx.x * TILE_B;

    // ---- persistent fills (once per CTA) ----
    {
        const float4* Wc1v = (const float4*)Wc1;     // 128x32 = 1024 float4; 8 f4/row
        for (int i4 = tid; i4 < (D * EDIM) / 4; i4 += THREADS) {
            float4 v = Wc1v[i4];
            v.x = to_tf32(v.x); v.y = to_tf32(v.y); v.z = to_tf32(v.z); v.w = to_tf32(v.w);
            *(float4*)&sWc[(i4 >> 3) * WC_LD + ((i4 & 7) << 2)] = v;
        }
        if (tid < 128) { sWs1[tid] = Ws1[tid]; sCacc[tid] = 0.f; }
        if (tid >= 128 && tid < 160) { sWc2[tid - 128] = Wc2[tid - 128]; }
        if (tid >= 160 && tid < 192) { sBc1[tid - 160] = bc1[tid - 160]; }
        if (tid == 192) {
            sConst[0] = bs1[0]; sConst[1] = Ws2[0];
            sConst[2] = bs2[0]; sConst[3] = bc2[0];
        }
    }

    // ---- prefetch W1[0] (raw fp32) + bias tile b1[0] ----
    {
        const float4* W1v = (const float4*)W1;                      // agent 0
        for (int i4 = tid; i4 < (D * HDIM) / 4; i4 += THREADS)      // 4096 f4; 32/row
            cp_async16(&sW[(i4 >> 5) * SW_LD + ((i4 & 31) << 2)], W1v + i4);
        cp_async_commit();
        const float4* b1v = (const float4*)b1;
        for (int i4 = tid; i4 < 16 * 32; i4 += THREADS)
            *(float4*)&sBT[(i4 >> 5) * BT_LD + ((i4 & 31) << 2)] = b1v[i4 & 31];
    }

    float qacc[32];
#pragma unroll
    for (int i = 0; i < 32; i++) qacc[i] = 0.f;

    using FragA = wmma::fragment<wmma::matrix_a, 16, 16, 8, wmma::precision::tf32, wmma::row_major>;
    using FragB = wmma::fragment<wmma::matrix_b, 16, 16, 8, wmma::precision::tf32, wmma::row_major>;
    using FragC = wmma::fragment<wmma::accumulator, 16, 16, 8, float>;

    const int rg = warp >> 1;   // 0..3 row-groups (32 rows each)
    const int cg = warp & 1;    // 0..1 col-groups

    for (int n = 0; n < NAGENT; n++) {
        const float* gS = states + ((size_t)n * BTOT + b0) * D;

        cp_async_wait_all();
        __syncthreads();        // W1[n] + b1 tile ready; prior-agent reads complete

        // ---- GEMM1: S(128x128) @ [W1 | Wc1](128x160) ----
        // cols: c0 = cg*80 + ct*16; c0<128 -> H1 (bias-init, relu+round, W from raw sW),
        //       c0>=128 -> Hc (zero-init, raw store, W from pre-converted sWc)
        {
            FragC acc[2][5];
#pragma unroll
            for (int ct = 0; ct < 5; ct++) {
                int c0 = cg * 80 + ct * 16;
#pragma unroll
                for (int rt = 0; rt < 2; rt++) {
                    if (c0 < 128)
                        wmma::load_matrix_sync(acc[rt][ct], sBT + c0, BT_LD, wmma::mem_row_major);
                    else
                        wmma::fill_fragment(acc[rt][ct], 0.f);
                }
            }
#pragma unroll 4
            for (int k0 = 0; k0 < D; k0 += 8) {
                FragA a[2];
#pragma unroll
                for (int rt = 0; rt < 2; rt++) {
                    wmma::load_matrix_sync(a[rt], gS + (rg * 32 + rt * 16) * D + k0, D);
#pragma unroll
                    for (int t = 0; t < a[rt].num_elements; t++) a[rt].x[t] = to_tf32(a[rt].x[t]);
                }
#pragma unroll
                for (int ct = 0; ct < 5; ct++) {
                    int c0 = cg * 80 + ct * 16;
                    FragB bf;
                    if (c0 < 128) {
                        wmma::load_matrix_sync(bf, sW + k0 * SW_LD + c0, SW_LD);
#pragma unroll
                        for (int t = 0; t < bf.num_elements; t++) bf.x[t] = to_tf32(bf.x[t]);
                    } else {
                        wmma::load_matrix_sync(bf, sWc + k0 * WC_LD + (c0 - 128), WC_LD);
                    }
#pragma unroll
                    for (int rt = 0; rt < 2; rt++)
                        wmma::mma_sync(acc[rt][ct], a[rt], bf, acc[rt][ct]);
                }
            }
#pragma unroll
            for (int ct = 0; ct < 5; ct++) {
                int c0 = cg * 80 + ct * 16;
#pragma unroll
                for (int rt = 0; rt < 2; rt++) {
                    int r0 = rg * 32 + rt * 16;
                    if (c0 < 128) {
#pragma unroll
                        for (int t = 0; t < acc[rt][ct].num_elements; t++) {
                            float v = acc[rt][ct].x[t];
                            acc[rt][ct].x[t] = to_tf32(v > 0.f ? v : 0.f);
                        }
                        wmma::store_matrix_sync(sHa + r0 * SH_LD + c0, acc[rt][ct], SH_LD, wmma::mem_row_major);
                    } else {
                        // raw Hc (bias+relu applied at consumption)
                        wmma::store_matrix_sync(sHb + r0 * SH_LD + (c0 - 128), acc[rt][ct], SH_LD, wmma::mem_row_major);
                    }
                }
            }
        }
        __syncthreads();

        // ---- issue W2 copy (drains during scalar work); fill sBT <- b2 ----
        {
            const float4* W2v = (const float4*)(W2 + (size_t)n * HDIM * HDIM);
            for (int i4 = tid; i4 < (HDIM * HDIM) / 4; i4 += THREADS)
                cp_async16(&sW[(i4 >> 5) * SW_LD + ((i4 & 31) << 2)], W2v + i4);
            cp_async_commit();
            const float4* b2v = (const float4*)(b2 + n * HDIM);
            for (int i4 = tid; i4 < 16 * 32; i4 += THREADS)
                *(float4*)&sBT[(i4 >> 5) * BT_LD + ((i4 & 31) << 2)] = b2v[i4 & 31];
        }
        // constraint: c_row += sum_e relu(HcRaw + bc1)_e * wc2_e  (+bc2); two chains for ILP
        if (tid < 128) {
            float s0 = 0.f, s1 = 0.f;
#pragma unroll
            for (int e = 0; e < 32; e += 2) {
                float h0 = sHb[tid * SH_LD + e]     + sBc1[e];
                float h1 = sHb[tid * SH_LD + e + 1] + sBc1[e + 1];
                s0 += (h0 > 0.f ? h0 : 0.f) * sWc2[e];
                s1 += (h1 > 0.f ? h1 : 0.f) * sWc2[e + 1];
            }
            sCacc[tid] += s0 + s1 + sConst[3];
        }
        // gate: sigmoid(ws2*relu(S.ws1 + bs1) + bs2); 8 warps x 16 rows
        for (int it = 0; it < TILE_B / 8; it++) {
            int r = warp + it * 8;
            const float4* srow = (const float4*)(gS + r * D);
            const float4* wv   = (const float4*)sWs1;
            float4 sv = srow[lane];
            float4 wvv = wv[lane];
            float p = sv.x * wvv.x + sv.y * wvv.y + sv.z * wvv.z + sv.w * wvv.w;
#pragma unroll
            for (int o = 16; o > 0; o >>= 1) p += __shfl_xor_sync(0xffffffffu, p, o);
            if (lane == 0) {
                float t = p + sConst[0]; t = t > 0.f ? t : 0.f;
                float z = sConst[1] * t + sConst[2];
                sScal[r] = 1.f / (1.f + __expf(-z));
            }
        }
        cp_async_wait_all();
        __syncthreads();   // W2+b2 ready; Hc consumed -> sHb writable

        // ---- GEMM2: H1(128x128) @ W2(128x128) -> sHb (bias-init, relu+round) ----
        {
            FragC acc[2][4];
#pragma unroll
            for (int ct = 0; ct < 4; ct++)
#pragma unroll
                for (int rt = 0; rt < 2; rt++)
                    wmma::load_matrix_sync(acc[rt][ct], sBT + cg * 64 + ct * 16, BT_LD, wmma::mem_row_major);

#pragma unroll 4
            for (int k0 = 0; k0 < HDIM; k0 += 8) {
                FragA a[2];
#pragma unroll
                for (int rt = 0; rt < 2; rt++)
                    wmma::load_matrix_sync(a[rt], sHa + (rg * 32 + rt * 16) * SH_LD + k0, SH_LD);
#pragma unroll
                for (int ct = 0; ct < 4; ct++) {
                    FragB bf;
                    wmma::load_matrix_sync(bf, sW + k0 * SW_LD + cg * 64 + ct * 16, SW_LD);
#pragma unroll
                    for (int t = 0; t < bf.num_elements; t++) bf.x[t] = to_tf32(bf.x[t]);
#pragma unroll
                    for (int rt = 0; rt < 2; rt++)
                        wmma::mma_sync(acc[rt][ct], a[rt], bf, acc[rt][ct]);
                }
            }
#pragma unroll
            for (int ct = 0; ct < 4; ct++)
#pragma unroll
                for (int rt = 0; rt < 2; rt++) {
#pragma unroll
                    for (int t = 0; t < acc[rt][ct].num_elements; t++) {
                        float v = acc[rt][ct].x[t];
                        acc[rt][ct].x[t] = to_tf32(v > 0.f ? v : 0.f);
                    }
                    wmma::store_matrix_sync(sHb + (rg * 32 + rt * 16) * SH_LD + cg * 64 + ct * 16,
                                            acc[rt][ct], SH_LD, wmma::mem_row_major);
                }
        }
        __syncthreads();   // sHb(H2) ready; sHa(H1) dead; sW free; sBT free

        // ---- issue W3 -> sHa cols 64..127 (group A), then W1[n+1] -> sW (group B);
        //      fill sBT <- b1[n+1], sB3 <- b3[n]. W1[n+1] drains across GEMM3+accum. ----
        {
            const float4* W3v = (const float4*)(W3 + (size_t)n * HDIM * ADIM);  // 2048 f4; 16/row
            for (int i4 = tid; i4 < (HDIM * ADIM) / 4; i4 += THREADS)
                cp_async16(&sHa[(i4 >> 4) * SH_LD + 64 + ((i4 & 15) << 2)], W3v + i4);
            cp_async_commit();                                                  // group A (W3)
            if (n + 1 < NAGENT) {
                const float4* W1v = (const float4*)(W1 + (size_t)(n + 1) * D * HDIM);
                for (int i4 = tid; i4 < (D * HDIM) / 4; i4 += THREADS)
                    cp_async16(&sW[(i4 >> 5) * SW_LD + ((i4 & 31) << 2)], W1v + i4);
                cp_async_commit();                                              // group B (W1[n+1])
                const float4* b1v = (const float4*)(b1 + (n + 1) * HDIM);
                for (int i4 = tid; i4 < 16 * 32; i4 += THREADS)
                    *(float4*)&sBT[(i4 >> 5) * BT_LD + ((i4 & 31) << 2)] = b1v[i4 & 31];
            }
            if (tid < 64) sB3[tid] = b3[n * ADIM + tid];
        }
        if (n + 1 < NAGENT) cp_async_wait_one_pending();   // W3 done, W1[n+1] may fly
        else                cp_async_wait_all();           // only W3 outstanding
        __syncthreads();

        // ---- GEMM3: H2(128x128)@sHb  x  W3 in sHa cols 64..127  ->  sHa cols 0..63 ----
        // B reads (cols 64..127) and output stores (cols 0..63) are column-disjoint.
        {
            FragC acc[2][2];
#pragma unroll
            for (int ct = 0; ct < 2; ct++)
#pragma unroll
                for (int rt = 0; rt < 2; rt++) wmma::fill_fragment(acc[rt][ct], 0.f);

#pragma unroll 4
            for (int k0 = 0; k0 < HDIM; k0 += 8) {
                FragA a[2];
#pragma unroll
                for (int rt = 0; rt < 2; rt++)
                    wmma::load_matrix_sync(a[rt], sHb + (rg * 32 + rt * 16) * SH_LD + k0, SH_LD);
#pragma unroll
                for (int ct = 0; ct < 2; ct++) {
                    FragB bf;
                    wmma::load_matrix_sync(bf, sHa + k0 * SH_LD + 64 + cg * 32 + ct * 16, SH_LD);
#pragma unroll
                    for (int t = 0; t < bf.num_elements; t++) bf.x[t] = to_tf32(bf.x[t]);
#pragma unroll
                    for (int rt = 0; rt < 2; rt++)
                        wmma::mma_sync(acc[rt][ct], a[rt], bf, acc[rt][ct]);
                }
            }
#pragma unroll
            for (int ct = 0; ct < 2; ct++)
#pragma unroll
                for (int rt = 0; rt < 2; rt++)
                    wmma::store_matrix_sync(sHa + (rg * 32 + rt * 16) * SH_LD + cg * 32 + ct * 16,
                                            acc[rt][ct], SH_LD, wmma::mem_row_major);
        }
        __syncthreads();

        // ---- gated accumulation: qacc += scal[r] * (Q[r][c] + b3[c]) ----
        {
            int c = tid & 63;
            int rbase = tid >> 6;    // 0..3
            float bc = sB3[c];
#pragma unroll
            for (int i = 0; i < 32; i++) {
                int r = rbase + (i << 2);
                qacc[i] += sScal[r] * (sHa[r * SH_LD + c] + bc);
            }
        }
        // loop-top wait+sync orders accumulation reads before next agent's writes
    }

    // ---- final: out = mean_n(scal*q) + mean_n(c); streaming stores (write-once data) ----
    {
        int c = tid & 63;
        int rbase = tid >> 6;
#pragma unroll
        for (int i = 0; i < 32; i++) {
            int r = rbase + (i << 2);
            __stcs(&out[(size_t)(b0 + r) * ADIM + c], 0.125f * (qacc[i] + sCacc[r]));
        }
    }
}

extern "C" void kernel_launch(void* const* d_in, const int* in_sizes, int n_in,
                              void* d_out, int out_size)
{
    const float* states = (const float*)d_in[0];
    const float* W1  = (const float*)d_in[1];
    const float* b1  = (const float*)d_in[2];
    const float* W2  = (const float*)d_in[3];
    const float* b2  = (const float*)d_in[4];
    const float* W3  = (const float*)d_in[5];
    const float* b3  = (const float*)d_in[6];
    // d_in[7..12]: Wq1,bq1,Wq2,bq2,Wk,bk — mathematically dead (softmax rows sum to 1,
    // and einsum('bnm,bna->bna') only ever sums attn over m)
    const float* Ws1 = (const float*)d_in[13];
    const float* bs1 = (const float*)d_in[14];
    const float* Ws2 = (const float*)d_in[15];
    const float* bs2 = (const float*)d_in[16];
    const float* Wc1 = (const float*)d_in[17];
    const float* bc1 = (const float*)d_in[18];
    const float* Wc2 = (const float*)d_in[19];
    const float* bc2 = (const float*)d_in[20];
    float* out = (float*)d_out;

    cudaFuncSetAttribute(qatten_kernel, cudaFuncAttributeMaxDynamicSharedMemorySize, SMEM_BYTES);

    dim3 grid(BTOT / TILE_B);   // 256 CTAs
    dim3 block(THREADS);
    qatten_kernel<<<grid, block, SMEM_BYTES>>>(states, W1, b1, W2, b2, W3, b3,
                                               Ws1, bs1, Ws2, bs2, Wc1, bc1, Wc2, bc2,
                                               out);
}